// round 1
// baseline (speedup 1.0000x reference)
#include <cuda_runtime.h>
#include <cuda_bf16.h>

#define BATCH 8
#define NBOX 2048
#define MAXDET 100
#define THREADS 256
#define MIN_SIZE 25.0f
#define IOU_THR 0.3f
#define SCORE_THR 0.001f
#define REMOVED -1.0f

// lexicographic argmax: (score desc, index asc) to match stable argsort order
__device__ __forceinline__ void amax2(float& s, int& i, float s2, int i2) {
    if (s2 > s || (s2 == s && i2 < i)) { s = s2; i = i2; }
}

__global__ __launch_bounds__(THREADS)
void nms_kernel(const float* __restrict__ boxes,
                const float* __restrict__ scores,
                float* __restrict__ out,
                int write_mask)
{
    __shared__ float4 sbox[NBOX];     // 32 KB
    __shared__ float  sscore[NBOX];   // 8 KB
    __shared__ float  ws[8];
    __shared__ int    wi[8];
    __shared__ float  s_best;
    __shared__ int    s_bidx;
    __shared__ float4 s_bbox;

    const int img = blockIdx.x;
    const int tid = threadIdx.x;

    // ---- stage boxes + filtered scores into shared ----
    const float4* bp = (const float4*)(boxes + (size_t)img * NBOX * 4);
    const float*  sp = scores + (size_t)img * NBOX;
    #pragma unroll
    for (int i = tid; i < NBOX; i += THREADS) {
        float4 b = bp[i];
        float w = b.z - b.x;
        float h = b.w - b.y;
        float s = sp[i];
        bool valid = (w >= MIN_SIZE) && (h >= MIN_SIZE) && (s >= SCORE_THR);
        sbox[i]   = b;
        sscore[i] = valid ? s : REMOVED;
    }

    // ---- init output: padding rows = [img, 0,0,0,0], mask = 0 ----
    float* outr = out + (size_t)img * MAXDET * 5;
    float* outm = out + (size_t)BATCH * MAXDET * 5 + (size_t)img * MAXDET;
    for (int i = tid; i < MAXDET; i += THREADS) {
        outr[i * 5 + 0] = (float)img;
        outr[i * 5 + 1] = 0.f;
        outr[i * 5 + 2] = 0.f;
        outr[i * 5 + 3] = 0.f;
        outr[i * 5 + 4] = 0.f;
        if (write_mask) outm[i] = 0.f;
    }
    __syncthreads();

    const int warp = tid >> 5;
    const int lane = tid & 31;

    for (int k = 0; k < MAXDET; k++) {
        // ---- parallel argmax over live scores ----
        float best = REMOVED;
        int   bidx = NBOX;
        #pragma unroll
        for (int i = tid; i < NBOX; i += THREADS)
            amax2(best, bidx, sscore[i], i);

        #pragma unroll
        for (int off = 16; off > 0; off >>= 1) {
            float os = __shfl_down_sync(0xffffffffu, best, off);
            int   oi = __shfl_down_sync(0xffffffffu, bidx, off);
            amax2(best, bidx, os, oi);
        }
        if (lane == 0) { ws[warp] = best; wi[warp] = bidx; }
        __syncthreads();
        if (warp == 0) {
            best = (lane < 8) ? ws[lane] : REMOVED;
            bidx = (lane < 8) ? wi[lane] : NBOX;
            #pragma unroll
            for (int off = 4; off > 0; off >>= 1) {
                float os = __shfl_down_sync(0xffffffffu, best, off);
                int   oi = __shfl_down_sync(0xffffffffu, bidx, off);
                amax2(best, bidx, os, oi);
            }
            if (lane == 0) {
                s_best = best;
                s_bidx = bidx;
                if (best > 0.f) s_bbox = sbox[bidx];
            }
        }
        __syncthreads();

        if (s_best <= 0.f) break;   // no live candidates left (uniform)

        float4 cb = s_bbox;
        if (tid == 0) {
            outr[k * 5 + 1] = cb.x;
            outr[k * 5 + 2] = cb.y;
            outr[k * 5 + 3] = cb.z;
            outr[k * 5 + 4] = cb.w;
            if (write_mask) outm[k] = 1.f;
        }

        // ---- suppress everything with IoU > 0.3 vs chosen (incl. itself) ----
        float areaC = (cb.z - cb.x) * (cb.w - cb.y);
        #pragma unroll
        for (int i = tid; i < NBOX; i += THREADS) {
            float s = sscore[i];
            if (s > 0.f) {
                float4 b = sbox[i];
                float ix = fminf(cb.z, b.z) - fmaxf(cb.x, b.x);
                float iy = fminf(cb.w, b.w) - fmaxf(cb.y, b.y);
                float inter = fmaxf(ix, 0.f) * fmaxf(iy, 0.f);
                float areaB = (b.z - b.x) * (b.w - b.y);
                float iou = inter / (areaC + areaB - inter);
                if (iou > IOU_THR) sscore[i] = REMOVED;
            }
        }
        __syncthreads();
    }
}

extern "C" void kernel_launch(void* const* d_in, const int* in_sizes, int n_in,
                              void* d_out, int out_size) {
    const float* boxes  = (const float*)d_in[0];   // [8,2048,4] f32
    const float* scores = (const float*)d_in[1];   // [8,2048]   f32
    float* out = (float*)d_out;
    // output = regions [B*100,5] flattened, then mask [B*100] as 0/1 floats
    int write_mask = (out_size >= BATCH * MAXDET * 5 + BATCH * MAXDET) ? 1 : 0;
    nms_kernel<<<BATCH, THREADS>>>(boxes, scores, out, write_mask);
}

// round 2
// speedup vs baseline: 2.9892x; 2.9892x over previous
#include <cuda_runtime.h>
#include <cuda_bf16.h>

#define BATCH 8
#define NBOX 2048
#define MAXDET 100
#define THREADS 512
#define PER (NBOX / THREADS)   // 4 boxes per thread
#define MIN_SIZE 25.0f
#define IOU_THR 0.3f
#define SCORE_THR 0.001f
#define DEAD -1.0f

// pack (score, idx) so that larger packed == (higher score, then smaller idx)
__device__ __forceinline__ unsigned long long pack_si(float s, int idx) {
    unsigned int sb = __float_as_uint(s);            // s > 0 -> monotonic bits
    unsigned int ib = ~(unsigned int)idx;            // smaller idx -> larger
    return ((unsigned long long)sb << 32) | ib;
}

__global__ __launch_bounds__(THREADS)
void nms_kernel(const float* __restrict__ boxes,
                const float* __restrict__ scores,
                float* __restrict__ out,
                int write_mask)
{
    __shared__ float4 sbox[NBOX];                    // 32 KB broadcast table
    __shared__ unsigned long long gbest[3];          // rotating argmax buffers

    const int img  = blockIdx.x;
    const int tid  = threadIdx.x;
    const int lane = tid & 31;

    // ---- stage: boxes to shared (for broadcast) + working set to registers ----
    const float4* bp = (const float4*)(boxes + (size_t)img * NBOX * 4);
    const float*  sp = scores + (size_t)img * NBOX;

    float4 mybox[PER];
    float  mys[PER];
    #pragma unroll
    for (int p = 0; p < PER; p++) {
        int i = p * THREADS + tid;
        float4 b = bp[i];
        float  s = sp[i];
        float w = b.z - b.x;
        float h = b.w - b.y;
        bool valid = (w >= MIN_SIZE) && (h >= MIN_SIZE) && (s >= SCORE_THR);
        sbox[i]   = b;
        mybox[p]  = b;
        mys[p]    = valid ? s : DEAD;
    }

    // ---- init output: padding rows = [img,0,0,0,0], mask = 0 ----
    float* outr = out + (size_t)img * MAXDET * 5;
    float* outm = out + (size_t)BATCH * MAXDET * 5 + (size_t)img * MAXDET;
    #pragma unroll
    for (int i = tid; i < MAXDET; i += THREADS) {
        outr[i * 5 + 0] = (float)img;
        outr[i * 5 + 1] = 0.f;
        outr[i * 5 + 2] = 0.f;
        outr[i * 5 + 3] = 0.f;
        outr[i * 5 + 4] = 0.f;
        if (write_mask) outm[i] = 0.f;
    }
    if (tid < 3) gbest[tid] = 0ULL;
    __syncthreads();

    // ---- initial local argmax (registers) ----
    unsigned long long lp = 0ULL;
    #pragma unroll
    for (int p = 0; p < PER; p++)
        if (mys[p] > 0.f) {
            unsigned long long c = pack_si(mys[p], p * THREADS + tid);
            if (c > lp) lp = c;
        }

    for (int k = 0; k < MAXDET; k++) {
        const int buf = k % 3;

        // warp-level max of packed (score, idx)
        #pragma unroll
        for (int off = 16; off > 0; off >>= 1) {
            unsigned long long o = __shfl_down_sync(0xffffffffu, lp, off);
            if (o > lp) lp = o;
        }
        if (lane == 0 && lp) atomicMax(&gbest[buf], lp);
        __syncthreads();

        unsigned long long w = gbest[buf];
        if (w == 0ULL) break;                        // nothing live (uniform)
        if (tid == 0) gbest[(k + 2) % 3] = 0ULL;     // safe: 2 barriers away

        int cidx = (int)(~(unsigned int)(w & 0xffffffffu));
        float4 cb = sbox[cidx];                      // broadcast, conflict-free

        if (tid == 0) {
            outr[k * 5 + 1] = cb.x;
            outr[k * 5 + 2] = cb.y;
            outr[k * 5 + 3] = cb.z;
            outr[k * 5 + 4] = cb.w;
            if (write_mask) outm[k] = 1.f;
        }

        // ---- fused: suppress vs chosen + compute next local argmax ----
        float areaC = (cb.z - cb.x) * (cb.w - cb.y);
        lp = 0ULL;
        #pragma unroll
        for (int p = 0; p < PER; p++) {
            float s = mys[p];
            if (s > 0.f) {
                float4 b = mybox[p];
                float ix = fminf(cb.z, b.z) - fmaxf(cb.x, b.x);
                float iy = fminf(cb.w, b.w) - fmaxf(cb.y, b.y);
                float inter = fmaxf(ix, 0.f) * fmaxf(iy, 0.f);
                float areaB = (b.z - b.x) * (b.w - b.y);
                float iou = inter / (areaC + areaB - inter);
                if (iou > IOU_THR) {
                    mys[p] = DEAD;                   // includes chosen itself
                } else {
                    unsigned long long c = pack_si(s, p * THREADS + tid);
                    if (c > lp) lp = c;
                }
            }
        }
    }
}

extern "C" void kernel_launch(void* const* d_in, const int* in_sizes, int n_in,
                              void* d_out, int out_size) {
    const float* boxes  = (const float*)d_in[0];   // [8,2048,4] f32
    const float* scores = (const float*)d_in[1];   // [8,2048]   f32
    float* out = (float*)d_out;
    int write_mask = (out_size >= BATCH * MAXDET * 5 + BATCH * MAXDET) ? 1 : 0;
    nms_kernel<<<BATCH, THREADS>>>(boxes, scores, out, write_mask);
}

// round 3
// speedup vs baseline: 9.5558x; 3.1968x over previous
#include <cuda_runtime.h>
#include <cuda_bf16.h>

#define BATCH 8
#define NBOX 2048
#define MAXDET 100
#define THREADS 128
#define PER (NBOX / THREADS)   // 16 boxes per thread
#define MIN_SIZE 25.0f
#define IOU_THR 0.3f
#define SCORE_THR 0.001f
#define DEAD -1.0f

// pack (score, idx): larger packed == (higher score, then smaller idx)
__device__ __forceinline__ unsigned long long pack_si(float s, int idx) {
    unsigned int sb = __float_as_uint(s);      // s > 0 -> monotonic bits
    unsigned int ib = ~(unsigned int)idx;
    return ((unsigned long long)sb << 32) | ib;
}

__global__ __launch_bounds__(THREADS, 1)
void nms_kernel(const float* __restrict__ boxes,
                const float* __restrict__ scores,
                float* __restrict__ out,
                int write_mask)
{
    __shared__ float4 sbox[NBOX];                    // 32 KB broadcast table
    __shared__ unsigned long long ws[2][4];          // double-buffered warp maxima

    const int img  = blockIdx.x;
    const int tid  = threadIdx.x;
    const int warp = tid >> 5;
    const int lane = tid & 31;

    const float4* bp = (const float4*)(boxes + (size_t)img * NBOX * 4);
    const float*  sp = scores + (size_t)img * NBOX;

    float4 mybox[PER];
    float  mys[PER];
    float  myarea[PER];
    #pragma unroll
    for (int p = 0; p < PER; p++) {
        int i = p * THREADS + tid;
        float4 b = bp[i];
        float  s = sp[i];
        float w = b.z - b.x;
        float h = b.w - b.y;
        bool valid = (w >= MIN_SIZE) && (h >= MIN_SIZE) && (s >= SCORE_THR);
        sbox[i]   = b;
        mybox[p]  = b;
        myarea[p] = w * h;
        mys[p]    = valid ? s : DEAD;
    }

    // init output padding: [img,0,0,0,0] rows, mask = 0
    float* outr = out + (size_t)img * MAXDET * 5;
    float* outm = out + (size_t)BATCH * MAXDET * 5 + (size_t)img * MAXDET;
    #pragma unroll
    for (int i = tid; i < MAXDET; i += THREADS) {
        outr[i * 5 + 0] = (float)img;
        outr[i * 5 + 1] = 0.f;
        outr[i * 5 + 2] = 0.f;
        outr[i * 5 + 3] = 0.f;
        outr[i * 5 + 4] = 0.f;
        if (write_mask) outm[i] = 0.f;
    }

    // initial thread-local argmax (ascending p => ascending idx; strict > keeps min idx)
    float bs = 0.f; int bi = 0;
    #pragma unroll
    for (int p = 0; p < PER; p++)
        if (mys[p] > bs) { bs = mys[p]; bi = p * THREADS + tid; }
    unsigned long long lp = (bs > 0.f) ? pack_si(bs, bi) : 0ULL;

    for (int k = 0; k < MAXDET; k++) {
        // warp max of packed value
        #pragma unroll
        for (int off = 16; off > 0; off >>= 1) {
            unsigned long long o = __shfl_xor_sync(0xffffffffu, lp, off);
            if (o > lp) lp = o;
        }
        if (lane == 0) ws[k & 1][warp] = lp;
        __syncthreads();

        // every thread reduces the 4 warp maxima
        unsigned long long w0 = ws[k & 1][0];
        unsigned long long w1 = ws[k & 1][1];
        unsigned long long w2 = ws[k & 1][2];
        unsigned long long w3 = ws[k & 1][3];
        unsigned long long w = w0 > w1 ? w0 : w1;
        unsigned long long v = w2 > w3 ? w2 : w3;
        if (v > w) w = v;

        if (w == 0ULL) break;                        // uniform exit

        int cidx = (int)(~(unsigned int)(w & 0xffffffffu));
        float4 cb = sbox[cidx];                      // conflict-free broadcast

        if (tid == 0) {
            outr[k * 5 + 1] = cb.x;
            outr[k * 5 + 2] = cb.y;
            outr[k * 5 + 3] = cb.z;
            outr[k * 5 + 4] = cb.w;
            if (write_mask) outm[k] = 1.f;
        }

        // fused: suppress vs chosen + next thread-local argmax (branchless, div-free)
        float areaC = (cb.z - cb.x) * (cb.w - cb.y);
        bs = 0.f; bi = 0;
        #pragma unroll
        for (int p = 0; p < PER; p++) {
            float4 b = mybox[p];
            float ix = fminf(cb.z, b.z) - fmaxf(cb.x, b.x);
            float iy = fminf(cb.w, b.w) - fmaxf(cb.y, b.y);
            float inter = fmaxf(ix, 0.f) * fmaxf(iy, 0.f);
            // iou > THR  <=>  inter > THR*(areaC + areaB - inter)
            float rhs = IOU_THR * (areaC + myarea[p] - inter);
            float s = (inter > rhs) ? DEAD : mys[p];
            mys[p] = s;
            if (s > bs) { bs = s; bi = p * THREADS + tid; }
        }
        lp = (bs > 0.f) ? pack_si(bs, bi) : 0ULL;
    }
}

extern "C" void kernel_launch(void* const* d_in, const int* in_sizes, int n_in,
                              void* d_out, int out_size) {
    const float* boxes  = (const float*)d_in[0];   // [8,2048,4] f32
    const float* scores = (const float*)d_in[1];   // [8,2048]   f32
    float* out = (float*)d_out;
    int write_mask = (out_size >= BATCH * MAXDET * 5 + BATCH * MAXDET) ? 1 : 0;
    nms_kernel<<<BATCH, THREADS>>>(boxes, scores, out, write_mask);
}

// round 4
// speedup vs baseline: 10.4875x; 1.0975x over previous
#include <cuda_runtime.h>
#include <cuda_bf16.h>

#define BATCH 8
#define NBOX 2048
#define MAXDET 100
#define THREADS 128
#define PER (NBOX / THREADS)   // 16 boxes per thread
#define MIN_SIZE 25.0f
#define SCORE_THR 0.001f
#define DEAD -1.0f
#define CIOU 0.23076923f       // 0.3 / 1.3 : iou>0.3 <=> inter > CIOU*(A+B)

// pack (score, idx): larger packed == (higher score, then smaller idx)
__device__ __forceinline__ unsigned long long pack_si(float s, int idx) {
    return ((unsigned long long)__float_as_uint(s) << 32) | (unsigned)(~idx);
}

// (m1,m2) sorted desc, (o1,o2) sorted desc -> (m1,m2) = exact top2 of union
__device__ __forceinline__ void merge_top2(unsigned long long& m1, unsigned long long& m2,
                                           unsigned long long o1, unsigned long long o2) {
    bool g = m1 > o1;
    unsigned long long hi  = g ? m1 : o1;
    unsigned long long mid = g ? (m2 > o1 ? m2 : o1) : (o2 > m1 ? o2 : m1);
    m1 = hi; m2 = mid;
}

__global__ __launch_bounds__(THREADS, 1)
void nms_kernel(const float* __restrict__ boxes,
                const float* __restrict__ scores,
                float* __restrict__ out,
                int write_mask)
{
    __shared__ float4 sbox[NBOX];                 // broadcast table (32 KB)
    __shared__ unsigned long long ws[2][8];       // [parity][warp*2+{0,1}]

    const int img  = blockIdx.x;
    const int tid  = threadIdx.x;
    const int warp = tid >> 5;
    const int lane = tid & 31;

    const float4* bp = (const float4*)(boxes + (size_t)img * NBOX * 4);
    const float*  sp = scores + (size_t)img * NBOX;

    float4 mybox[PER];
    float  mys[PER];
    float  myca[PER];    // CIOU * area
    #pragma unroll
    for (int p = 0; p < PER; p++) {
        int i = p * THREADS + tid;
        float4 b = bp[i];
        float  s = sp[i];
        float w = b.z - b.x;
        float h = b.w - b.y;
        bool valid = (w >= MIN_SIZE) && (h >= MIN_SIZE) && (s >= SCORE_THR);
        sbox[i]   = b;
        mybox[p]  = b;
        myca[p]   = CIOU * (w * h);
        mys[p]    = valid ? s : DEAD;
    }

    // init output padding: [img,0,0,0,0] rows, mask = 0
    float* outr = out + (size_t)img * MAXDET * 5;
    float* outm = out + (size_t)BATCH * MAXDET * 5 + (size_t)img * MAXDET;
    #pragma unroll
    for (int i = tid; i < MAXDET; i += THREADS) {
        outr[i * 5 + 0] = (float)img;
        outr[i * 5 + 1] = 0.f;
        outr[i * 5 + 2] = 0.f;
        outr[i * 5 + 3] = 0.f;
        outr[i * 5 + 4] = 0.f;
        if (write_mask) outm[i] = 0.f;
    }

    // prologue: thread-local exact top-2 (ascending idx, strict > => min-idx tie-break)
    float b1 = 0.f, b2 = 0.f; int i1 = 0, i2 = 0;
    #pragma unroll
    for (int p = 0; p < PER; p++) {
        float s = mys[p]; int idx = p * THREADS + tid;
        bool g1 = s > b1;
        float ds = g1 ? b1 : s;  int di = g1 ? i1 : idx;
        b1 = g1 ? s : b1;        i1 = g1 ? idx : i1;
        bool g2 = ds > b2;
        b2 = g2 ? ds : b2;       i2 = g2 ? di : i2;
    }
    unsigned long long lp1 = (b1 > 0.f) ? pack_si(b1, i1) : 0ULL;
    unsigned long long lp2 = (b2 > 0.f) ? pack_si(b2, i2) : 0ULL;

    int k = 0, par = 0;
    while (k < MAXDET) {
        // warp-level exact top-2 (pairwise butterfly merge)
        unsigned long long m1 = lp1, m2 = lp2;
        #pragma unroll
        for (int off = 16; off > 0; off >>= 1) {
            unsigned long long o1 = __shfl_xor_sync(0xffffffffu, m1, off);
            unsigned long long o2 = __shfl_xor_sync(0xffffffffu, m2, off);
            merge_top2(m1, m2, o1, o2);
        }
        if (lane == 0) { ws[par][warp * 2] = m1; ws[par][warp * 2 + 1] = m2; }
        __syncthreads();

        // merge 4 warp pairs -> exact global top-2 (every thread, redundantly)
        unsigned long long g1 = 0ULL, g2 = 0ULL;
        #pragma unroll
        for (int j = 0; j < 4; j++)
            merge_top2(g1, g2, ws[par][2 * j], ws[par][2 * j + 1]);
        par ^= 1;

        if (g1 == 0ULL) break;                     // nothing live (uniform)

        int c1 = (int)~(unsigned)(g1 & 0xffffffffu);
        int c2 = (g2 != 0ULL) ? (int)~(unsigned)(g2 & 0xffffffffu) : c1;
        float4 cb1 = sbox[c1];
        float4 cb2 = sbox[c2];

        // accept t2 iff it exists and doesn't overlap t1
        float ca1 = CIOU * ((cb1.z - cb1.x) * (cb1.w - cb1.y));
        float ca2 = CIOU * ((cb2.z - cb2.x) * (cb2.w - cb2.y));
        float ox = fminf(cb1.z, cb2.z) - fmaxf(cb1.x, cb2.x);
        float oy = fminf(cb1.w, cb2.w) - fmaxf(cb1.y, cb2.y);
        float ov = fmaxf(ox, 0.f) * fmaxf(oy, 0.f);
        bool sel2 = (g2 != 0ULL) && !(ov > ca1 + ca2);
        if (!sel2) { cb2 = cb1; ca2 = ca1; }       // double-suppress by t1: idempotent

        if (tid == 0) {
            outr[k * 5 + 1] = cb1.x;
            outr[k * 5 + 2] = cb1.y;
            outr[k * 5 + 3] = cb1.z;
            outr[k * 5 + 4] = cb1.w;
            if (write_mask) outm[k] = 1.f;
            if (sel2 && k + 1 < MAXDET) {
                outr[(k + 1) * 5 + 1] = cb2.x;
                outr[(k + 1) * 5 + 2] = cb2.y;
                outr[(k + 1) * 5 + 3] = cb2.z;
                outr[(k + 1) * 5 + 4] = cb2.w;
                if (write_mask) outm[k + 1] = 1.f;
            }
        }

        // fused: suppress vs cb1 & cb2 + next thread-local top-2
        b1 = 0.f; b2 = 0.f; i1 = 0; i2 = 0;
        #pragma unroll
        for (int p = 0; p < PER; p++) {
            float4 b = mybox[p];
            float ix1 = fminf(cb1.z, b.z) - fmaxf(cb1.x, b.x);
            float iy1 = fminf(cb1.w, b.w) - fmaxf(cb1.y, b.y);
            float in1 = fmaxf(ix1, 0.f) * fmaxf(iy1, 0.f);
            float ix2 = fminf(cb2.z, b.z) - fmaxf(cb2.x, b.x);
            float iy2 = fminf(cb2.w, b.w) - fmaxf(cb2.y, b.y);
            float in2 = fmaxf(ix2, 0.f) * fmaxf(iy2, 0.f);
            bool dead = (in1 > ca1 + myca[p]) || (in2 > ca2 + myca[p]);
            float s = dead ? DEAD : mys[p];
            mys[p] = s;
            int idx = p * THREADS + tid;
            bool g1f = s > b1;
            float ds = g1f ? b1 : s;  int di = g1f ? i1 : idx;
            b1 = g1f ? s : b1;        i1 = g1f ? idx : i1;
            bool g2f = ds > b2;
            b2 = g2f ? ds : b2;       i2 = g2f ? di : i2;
        }
        lp1 = (b1 > 0.f) ? pack_si(b1, i1) : 0ULL;
        lp2 = (b2 > 0.f) ? pack_si(b2, i2) : 0ULL;

        k += sel2 ? 2 : 1;
    }
}

extern "C" void kernel_launch(void* const* d_in, const int* in_sizes, int n_in,
                              void* d_out, int out_size) {
    const float* boxes  = (const float*)d_in[0];   // [8,2048,4] f32
    const float* scores = (const float*)d_in[1];   // [8,2048]   f32
    float* out = (float*)d_out;
    int write_mask = (out_size >= BATCH * MAXDET * 5 + BATCH * MAXDET) ? 1 : 0;
    nms_kernel<<<BATCH, THREADS>>>(boxes, scores, out, write_mask);
}